// round 15
// baseline (speedup 1.0000x reference)
#include <cuda_runtime.h>
#include <cuda_bf16.h>
#include <cstdint>

// Problem constants
#define BB 2
#define TT 512
#define UU 48
#define DD 512
#define HH 1024
#define KK 128
#define SEG_ELEMS (BB*KK*TT)   // 131072 floats, first part of d_out

// Scratch (allocation-free rule: __device__ globals)
__device__ float g_img_pre[BB*TT*HH];           // [(b*T+t)][h] : img @ Wi^T (fp32)
__device__ float g_lab_pre[BB*UU*HH];           // [(b*U+u)][h] : lab @ Wl^T + b1 (fp32)
__device__ __nv_bfloat16 g_w2bf[KK*HH];         // W2 bf16, native (k,h) layout = B^T row-major

__device__ __forceinline__ float tanh_hw(float x){
    asm("tanh.approx.f32 %0, %0;" : "+f"(x)); return x;
}
__device__ __forceinline__ uint32_t smem_u32(const void* p){
    uint32_t a;
    asm("{ .reg .u64 t; cvta.to.shared.u64 t, %1; cvt.u32.u64 %0, t; }" : "=r"(a) : "l"(p));
    return a;
}
__device__ __forceinline__ void ldsm_x4(uint32_t* r, uint32_t addr){
    asm volatile("ldmatrix.sync.aligned.m8n8.x4.shared.b16 {%0,%1,%2,%3}, [%4];"
        : "=r"(r[0]), "=r"(r[1]), "=r"(r[2]), "=r"(r[3]) : "r"(addr));
}
__device__ __forceinline__ void mma16816(float* c, const uint32_t* a, uint32_t b0, uint32_t b1){
    asm volatile("mma.sync.aligned.m16n8k16.row.col.f32.bf16.bf16.f32 "
        "{%0,%1,%2,%3}, {%4,%5,%6,%7}, {%8,%9}, {%0,%1,%2,%3};"
        : "+f"(c[0]), "+f"(c[1]), "+f"(c[2]), "+f"(c[3])
        : "r"(a[0]), "r"(a[1]), "r"(a[2]), "r"(a[3]), "r"(b0), "r"(b1));
}
__device__ __forceinline__ void mma1688_tf32(float* c, const uint32_t* a, uint32_t b0, uint32_t b1){
    asm volatile("mma.sync.aligned.m16n8k8.row.col.f32.tf32.tf32.f32 "
        "{%0,%1,%2,%3}, {%4,%5,%6,%7}, {%8,%9}, {%0,%1,%2,%3};"
        : "+f"(c[0]), "+f"(c[1]), "+f"(c[2]), "+f"(c[3])
        : "r"(a[0]), "r"(a[1]), "r"(a[2]), "r"(a[3]), "r"(b0), "r"(b1));
}
__device__ __forceinline__ uint32_t sw_addr(uint32_t base, int row, int colb){
    uint32_t rel = (uint32_t)(row*128 + colb);
    return base + (rel ^ ((rel >> 3) & 0x70));
}
__device__ __forceinline__ void cp_async16(uint32_t dst, const void* src){
    asm volatile("cp.async.cg.shared.global [%0], [%1], 16;" :: "r"(dst), "l"(src));
}
__device__ __forceinline__ void cp_commit(){ asm volatile("cp.async.commit_group;" ::: "memory"); }
__device__ __forceinline__ void cp_wait0(){ asm volatile("cp.async.wait_group 0;" ::: "memory"); }
__device__ __forceinline__ uint32_t f2tf32(float x){
    uint32_t r; asm("cvt.rna.tf32.f32 %0, %1;" : "=r"(r) : "f"(x)); return r;
}
__device__ __forceinline__ float lds32(uint32_t addr){
    float v; asm volatile("ld.shared.f32 %0, [%1];" : "=f"(v) : "r"(addr)); return v;
}

// ---------------------------------------------------------------------------
// Prep kernel, tf32 tensor-core: 3 NT-GEMMs + W2 bf16 convert. 88 CTAs.
// (unchanged from R12 — measured good)
// ---------------------------------------------------------------------------
#define PSM_A0 0u
#define PSM_A1 16384u
#define PSM_B0 32768u
#define PSM_B1 49152u
#define PSM_TOTAL 65536

__global__ __launch_bounds__(256, 2) void prep_tc_kernel(
    const float* __restrict__ img, const float* __restrict__ lab,
    const float* __restrict__ W1, const float* __restrict__ b1,
    const float* __restrict__ convw, const float* __restrict__ convb,
    const float* __restrict__ masks, const float* __restrict__ W2,
    float* __restrict__ out)
{
    extern __shared__ char dsm[];
    const int bx  = blockIdx.x;
    const int tid = threadIdx.x;

    if (bx >= 80){
        int base = (bx - 80)*16384 + tid*4;
        #pragma unroll
        for (int q = 0; q < 16; q++){
            int i = base + q*1024;
            float4 wv = *(const float4*)&W2[i];
            __nv_bfloat162 p0 = __floats2bfloat162_rn(wv.x, wv.y);
            __nv_bfloat162 p1 = __floats2bfloat162_rn(wv.z, wv.w);
            uint2 u; u.x = *(uint32_t*)&p0; u.y = *(uint32_t*)&p1;
            *(uint2*)&g_w2bf[i] = u;
        }
        return;
    }

    const uint32_t sb = smem_u32(dsm);
    const float* A; const float* Bp;
    int ldb, M, m0, n0, job;
    if (bx < 64)      { job=0; A=img; Bp=W1+DD; ldb=2*DD; M=BB*TT; m0=(bx&7)*128;  n0=(bx>>3)*128; }
    else if (bx < 72) { job=1; A=lab; Bp=W1;    ldb=2*DD; M=BB*UU; m0=0;           n0=(bx-64)*128; }
    else              { job=2; A=img; Bp=convw; ldb=DD;   M=BB*TT; m0=(bx-72)*128; n0=0; }

    const int wid  = tid >> 5;
    const int lane = tid & 31;
    const int warp_m = wid & 3;
    const int warp_n = wid >> 2;
    const int lane4 = lane & 3;
    const int grp   = lane >> 2;

    const int r    = tid >> 1;
    const int cb0  = (tid & 1) * 16;
    const bool avalid = (m0 + r) < M;
    const float* arow = A  + (size_t)(m0 + r)*DD;
    const float* brow = Bp + (size_t)(n0 + r)*ldb;

    float acc[2][8][4];
    #pragma unroll
    for (int mi = 0; mi < 2; mi++)
        #pragma unroll
        for (int ni = 0; ni < 8; ni++)
            #pragma unroll
            for (int j = 0; j < 4; j++) acc[mi][ni][j] = 0.f;

    #pragma unroll
    for (int kk = 0; kk < 4; kk++){
        int col = cb0 + kk*4;
        float4 av = avalid ? *(const float4*)&arow[col] : make_float4(0,0,0,0);
        float4 bv = *(const float4*)&brow[col];
        uint4 at, bt;
        at.x = f2tf32(av.x); at.y = f2tf32(av.y); at.z = f2tf32(av.z); at.w = f2tf32(av.w);
        bt.x = f2tf32(bv.x); bt.y = f2tf32(bv.y); bt.z = f2tf32(bv.z); bt.w = f2tf32(bv.w);
        uint32_t aa = sw_addr(sb + PSM_A0, r, col*4);
        uint32_t ba = sw_addr(sb + PSM_B0, r, col*4);
        asm volatile("st.shared.v4.b32 [%0], {%1,%2,%3,%4};"
            :: "r"(aa), "r"(at.x), "r"(at.y), "r"(at.z), "r"(at.w));
        asm volatile("st.shared.v4.b32 [%0], {%1,%2,%3,%4};"
            :: "r"(ba), "r"(bt.x), "r"(bt.y), "r"(bt.z), "r"(bt.w));
    }
    __syncthreads();

    for (int c = 0; c < 16; c++){
        const int s  = c & 1;
        const int dn = c*32 + 32;
        const uint32_t Ab = sb + (s ? PSM_A1 : PSM_A0);
        const uint32_t Bb = sb + (s ? PSM_B1 : PSM_B0);
        const uint32_t An = sb + (s ? PSM_A0 : PSM_A1);
        const uint32_t Bn = sb + (s ? PSM_B0 : PSM_B1);

        #pragma unroll
        for (int kk = 0; kk < 4; kk++){
            float4 av, bv;
            if (c < 15){
                int col = dn + cb0 + kk*4;
                av = avalid ? *(const float4*)&arow[col] : make_float4(0,0,0,0);
                bv = *(const float4*)&brow[col];
            }
            const int ca = (kk*8 + lane4)*4;
            const int cc = (kk*8 + lane4 + 4)*4;
            uint32_t af[2][4];
            #pragma unroll
            for (int mi = 0; mi < 2; mi++){
                int rb = warp_m*32 + mi*16;
                af[mi][0] = __float_as_uint(lds32(sw_addr(Ab, rb + grp,     ca)));
                af[mi][1] = __float_as_uint(lds32(sw_addr(Ab, rb + grp + 8, ca)));
                af[mi][2] = __float_as_uint(lds32(sw_addr(Ab, rb + grp,     cc)));
                af[mi][3] = __float_as_uint(lds32(sw_addr(Ab, rb + grp + 8, cc)));
            }
            #pragma unroll
            for (int ni = 0; ni < 8; ni++){
                int rn = warp_n*64 + ni*8 + grp;
                uint32_t b0 = __float_as_uint(lds32(sw_addr(Bb, rn, ca)));
                uint32_t b1 = __float_as_uint(lds32(sw_addr(Bb, rn, cc)));
                mma1688_tf32(acc[0][ni], af[0], b0, b1);
                mma1688_tf32(acc[1][ni], af[1], b0, b1);
            }
            if (c < 15){
                int col = cb0 + kk*4;
                uint4 at, bt;
                at.x = f2tf32(av.x); at.y = f2tf32(av.y); at.z = f2tf32(av.z); at.w = f2tf32(av.w);
                bt.x = f2tf32(bv.x); bt.y = f2tf32(bv.y); bt.z = f2tf32(bv.z); bt.w = f2tf32(bv.w);
                asm volatile("st.shared.v4.b32 [%0], {%1,%2,%3,%4};"
                    :: "r"(sw_addr(An, r, col*4)), "r"(at.x), "r"(at.y), "r"(at.z), "r"(at.w));
                asm volatile("st.shared.v4.b32 [%0], {%1,%2,%3,%4};"
                    :: "r"(sw_addr(Bn, r, col*4)), "r"(bt.x), "r"(bt.y), "r"(bt.z), "r"(bt.w));
            }
        }
        __syncthreads();
    }

    if (job == 0){
        #pragma unroll
        for (int mi = 0; mi < 2; mi++)
            #pragma unroll
            for (int h = 0; h < 2; h++){
                int m = m0 + warp_m*32 + mi*16 + grp + 8*h;
                float* orow = g_img_pre + (size_t)m*HH + n0 + warp_n*64;
                #pragma unroll
                for (int ni = 0; ni < 8; ni++)
                    *(float2*)&orow[ni*8 + 2*lane4] =
                        make_float2(acc[mi][ni][2*h], acc[mi][ni][2*h+1]);
            }
    } else if (job == 1){
        #pragma unroll
        for (int mi = 0; mi < 2; mi++)
            #pragma unroll
            for (int h = 0; h < 2; h++){
                int m = warp_m*32 + mi*16 + grp + 8*h;
                if (m < BB*UU){
                    float* orow = g_lab_pre + (size_t)m*HH + n0 + warp_n*64;
                    #pragma unroll
                    for (int ni = 0; ni < 8; ni++){
                        int n = ni*8 + 2*lane4;
                        float2 bb = *(const float2*)&b1[n0 + warp_n*64 + n];
                        *(float2*)&orow[n] =
                            make_float2(acc[mi][ni][2*h] + bb.x, acc[mi][ni][2*h+1] + bb.y);
                    }
                }
            }
    } else {
        #pragma unroll
        for (int mi = 0; mi < 2; mi++)
            #pragma unroll
            for (int h = 0; h < 2; h++){
                int m = m0 + warp_m*32 + mi*16 + grp + 8*h;
                float mk = masks[m];
                int b = m >> 9, t = m & 511;
                #pragma unroll
                for (int ni = 0; ni < 8; ni++){
                    int n = warp_n*64 + ni*8 + 2*lane4;
                    float2 cbv = *(const float2*)&convb[n];
                    out[(b*KK + n  )*TT + t] = (acc[mi][ni][2*h  ] + cbv.x)*mk;
                    out[(b*KK + n+1)*TT + t] = (acc[mi][ni][2*h+1] + cbv.y)*mk;
                }
            }
    }
}

// ---------------------------------------------------------------------------
// Joint kernel: 64(t) x 128(k) tile, occ 3 (85-reg cap), bf16 HMMA.
// 768 CTAs (96 pairs x 8 t-tiles); 8 warps = 4(m:16 rows) x 2(n:64 cols),
// 32 accs/thread. Double-buffered; A prefetch split in two 8-float halves
// interleaved between kstep pairs (<=8 extra live regs).
// ---------------------------------------------------------------------------
#define JSM_A0   0u
#define JSM_A1   8192u
#define JSM_B0   16384u
#define JSM_B1   32768u
#define JSM_B2S  49152u
#define JSM_RM   49664u   // 2*64 floats
#define JSM_RS   50176u
#define JSM_TOTAL 50688

__global__ __launch_bounds__(256, 3)
void joint_mma_kernel(const float* __restrict__ b2, float* __restrict__ out)
{
    extern __shared__ char dsm[];
    const uint32_t sb = smem_u32(dsm);
    float* b2s  = (float*)(dsm + JSM_B2S);
    float* redm = (float*)(dsm + JSM_RM);
    float* reds = (float*)(dsm + JSM_RS);

    const int tid  = threadIdx.x;
    const int wid  = tid >> 5;
    const int lane = tid & 31;
    const int warp_m = wid & 3;     // 16 t-rows each
    const int warp_n = wid >> 2;    // 64 k-cols each
    const int lane4 = lane & 3;
    const int grp   = lane >> 2;

    const int pair = blockIdx.x >> 3;        // b*U+u
    const int t0   = (blockIdx.x & 7) * 64;
    const int b    = pair / UU;

    if (tid < KK) b2s[tid] = b2[tid];

    const float* imgp = g_img_pre + (size_t)(b*TT + t0)*HH;
    const float* labp = g_lab_pre + (size_t)pair*HH;

    // A staging role: row ra (0..63), 16 h-values at qa
    const int ra = tid >> 2;
    const int qa = (tid & 3) * 16;
    const uint32_t arel = (uint32_t)(ra*128 + qa*2);
    // B staging role: row rb (0..127), 32 h-values at hbB
    const int rb = tid >> 1;
    const int hbB = (tid & 1) * 32;
    const uint32_t brel = (uint32_t)(rb*128 + hbB*2);

    float acc[8][4];
    #pragma unroll
    for (int ni = 0; ni < 8; ni++)
        #pragma unroll
        for (int j = 0; j < 4; j++) acc[ni][j] = 0.f;

    // -------- prologue: stage chunk 0 into buffer 0 --------
    {
        const char* wsrc = (const char*)(g_w2bf + (size_t)rb*HH + hbB);
        #pragma unroll
        for (int j = 0; j < 4; j++){
            uint32_t rel = brel + j*16;
            cp_async16(sb + JSM_B0 + (rel ^ ((rel >> 3) & 0x70)), wsrc + j*16);
        }
        cp_commit();
        const float* ia = imgp + (size_t)ra*HH + qa;
        const float* la = labp + qa;
        #pragma unroll
        for (int j = 0; j < 2; j++){
            float4 i0 = *(const float4*)&ia[j*8];
            float4 i1 = *(const float4*)&ia[j*8+4];
            float4 l0 = *(const float4*)&la[j*8];
            float4 l1 = *(const float4*)&la[j*8+4];
            __nv_bfloat162 p0 = __floats2bfloat162_rn(tanh_hw(i0.x+l0.x), tanh_hw(i0.y+l0.y));
            __nv_bfloat162 p1 = __floats2bfloat162_rn(tanh_hw(i0.z+l0.z), tanh_hw(i0.w+l0.w));
            __nv_bfloat162 p2 = __floats2bfloat162_rn(tanh_hw(i1.x+l1.x), tanh_hw(i1.y+l1.y));
            __nv_bfloat162 p3 = __floats2bfloat162_rn(tanh_hw(i1.z+l1.z), tanh_hw(i1.w+l1.w));
            uint32_t rel = arel + j*16;
            uint32_t addr = sb + JSM_A0 + (rel ^ ((rel >> 3) & 0x70));
            asm volatile("st.shared.v4.b32 [%0], {%1,%2,%3,%4};"
                :: "r"(addr), "r"(*(uint32_t*)&p0), "r"(*(uint32_t*)&p1),
                   "r"(*(uint32_t*)&p2), "r"(*(uint32_t*)&p3));
        }
        cp_wait0();
    }
    __syncthreads();

    // -------- main loop --------
    for (int c = 0; c < 16; c++){
        const int s  = c & 1;
        const int hn = c*64 + 64;
        const uint32_t Ab = sb + (s ? JSM_A1 : JSM_A0);
        const uint32_t Bb = sb + (s ? JSM_B1 : JSM_B0);
        const uint32_t An = sb + (s ? JSM_A0 : JSM_A1);
        const uint32_t Bn = sb + (s ? JSM_B0 : JSM_B1);

        if (c < 15){
            const char* wsrc = (const char*)(g_w2bf + (size_t)rb*HH + hn + hbB);
            #pragma unroll
            for (int j = 0; j < 4; j++){
                uint32_t rel = brel + j*16;
                cp_async16(Bn + (rel ^ ((rel >> 3) & 0x70)), wsrc + j*16);
            }
            cp_commit();
        }

        // first half of A(c+1) prefetch
        float4 p0, p1;
        if (c < 15){
            const float* ia = imgp + (size_t)ra*HH + hn + qa;
            p0 = *(const float4*)&ia[0];
            p1 = *(const float4*)&ia[4];
        }

        #pragma unroll
        for (int half = 0; half < 2; half++){
            #pragma unroll
            for (int k2 = 0; k2 < 2; k2++){
                const int kk = half*2 + k2;
                const int colb = kk*32 + (lane >> 4)*16;
                uint32_t af[4];
                ldsm_x4(af, sw_addr(Ab, warp_m*16 + (lane & 15), colb));
                uint32_t bf[4][4];
                #pragma unroll
                for (int p = 0; p < 4; p++)
                    ldsm_x4(bf[p], sw_addr(Bb, warp_n*64 + p*16 + (lane & 15), colb));
                #pragma unroll
                for (int p = 0; p < 4; p++){
                    mma16816(acc[2*p  ], af, bf[p][0], bf[p][2]);
                    mma16816(acc[2*p+1], af, bf[p][1], bf[p][3]);
                }
            }
            // after each kstep pair: finish this half of A(c+1), start next half
            if (c < 15){
                const float* la = labp + hn + qa + half*8;
                float4 l0 = *(const float4*)&la[0];
                float4 l1 = *(const float4*)&la[4];
                __nv_bfloat162 q0 = __floats2bfloat162_rn(tanh_hw(p0.x+l0.x), tanh_hw(p0.y+l0.y));
                __nv_bfloat162 q1 = __floats2bfloat162_rn(tanh_hw(p0.z+l0.z), tanh_hw(p0.w+l0.w));
                __nv_bfloat162 q2 = __floats2bfloat162_rn(tanh_hw(p1.x+l1.x), tanh_hw(p1.y+l1.y));
                __nv_bfloat162 q3 = __floats2bfloat162_rn(tanh_hw(p1.z+l1.z), tanh_hw(p1.w+l1.w));
                uint32_t rel = arel + half*16;
                uint32_t addr = An + (rel ^ ((rel >> 3) & 0x70));
                asm volatile("st.shared.v4.b32 [%0], {%1,%2,%3,%4};"
                    :: "r"(addr), "r"(*(uint32_t*)&q0), "r"(*(uint32_t*)&q1),
                       "r"(*(uint32_t*)&q2), "r"(*(uint32_t*)&q3));
                if (half == 0){
                    const float* ia = imgp + (size_t)ra*HH + hn + qa + 8;
                    p0 = *(const float4*)&ia[0];
                    p1 = *(const float4*)&ia[4];
                }
            }
        }
        if (c < 15) cp_wait0();
        __syncthreads();
    }

    // ---- epilogue: +b2, log_softmax over k (row split across 2 n-warps) ----
    #pragma unroll
    for (int ni = 0; ni < 8; ni++){
        float2 bv = *(const float2*)&b2s[warp_n*64 + ni*8 + 2*lane4];
        acc[ni][0] += bv.x; acc[ni][1] += bv.y;
        acc[ni][2] += bv.x; acc[ni][3] += bv.y;
    }
    float rm[2];
    #pragma unroll
    for (int h = 0; h < 2; h++){
        float m = -1e30f;
        #pragma unroll
        for (int ni = 0; ni < 8; ni++)
            m = fmaxf(m, fmaxf(acc[ni][2*h], acc[ni][2*h+1]));
        #pragma unroll
        for (int d = 1; d < 4; d <<= 1)
            m = fmaxf(m, __shfl_xor_sync(0xffffffffu, m, d));
        rm[h] = m;
    }
    if (lane4 == 0){
        #pragma unroll
        for (int h = 0; h < 2; h++)
            redm[warp_n*64 + warp_m*16 + grp + 8*h] = rm[h];
    }
    __syncthreads();
    float mx[2], sm[2];
    #pragma unroll
    for (int h = 0; h < 2; h++){
        int row = warp_m*16 + grp + 8*h;
        mx[h] = fmaxf(redm[row], redm[64 + row]);
        float s = 0.f;
        #pragma unroll
        for (int ni = 0; ni < 8; ni++)
            s += __expf(acc[ni][2*h] - mx[h]) + __expf(acc[ni][2*h+1] - mx[h]);
        #pragma unroll
        for (int d = 1; d < 4; d <<= 1)
            s += __shfl_xor_sync(0xffffffffu, s, d);
        sm[h] = s;
    }
    if (lane4 == 0){
        #pragma unroll
        for (int h = 0; h < 2; h++)
            reds[warp_n*64 + warp_m*16 + grp + 8*h] = sm[h];
    }
    __syncthreads();
    float* outj = out + SEG_ELEMS + (size_t)(pair*TT + t0)*KK;
    #pragma unroll
    for (int h = 0; h < 2; h++){
        int row = warp_m*16 + grp + 8*h;
        float L = mx[h] + __logf(reds[row] + reds[64 + row]);
        float* orow = outj + row*KK + warp_n*64;
        #pragma unroll
        for (int ni = 0; ni < 8; ni++)
            *(float2*)&orow[ni*8 + 2*lane4] =
                make_float2(acc[ni][2*h] - L, acc[ni][2*h+1] - L);
    }
}

// ---------------------------------------------------------------------------
extern "C" void kernel_launch(void* const* d_in, const int* in_sizes, int n_in,
                              void* d_out, int out_size)
{
    (void)in_sizes; (void)n_in; (void)out_size;
    const float* img   = (const float*)d_in[0];  // (B,T,D)
    const float* lab   = (const float*)d_in[1];  // (B,U,D)
    const float* masks = (const float*)d_in[2];  // (B,1,T)
    const float* W1    = (const float*)d_in[3];  // (H,2D)
    const float* b1    = (const float*)d_in[4];  // (H)
    const float* W2    = (const float*)d_in[5];  // (K,H)
    const float* b2    = (const float*)d_in[6];  // (K)
    const float* convw = (const float*)d_in[7];  // (K,D)
    const float* convb = (const float*)d_in[8];  // (K)
    float* out = (float*)d_out;

    cudaFuncSetAttribute(prep_tc_kernel,
                         cudaFuncAttributeMaxDynamicSharedMemorySize, PSM_TOTAL);
    cudaFuncSetAttribute(joint_mma_kernel,
                         cudaFuncAttributeMaxDynamicSharedMemorySize, JSM_TOTAL);

    prep_tc_kernel<<<88, 256, PSM_TOTAL>>>(img, lab, W1, b1, convw, convb, masks, W2, out);
    joint_mma_kernel<<<768, 256, JSM_TOTAL>>>(b2, out);
}

// round 16
// speedup vs baseline: 1.0003x; 1.0003x over previous
#include <cuda_runtime.h>
#include <cuda_bf16.h>
#include <cstdint>

// Problem constants
#define BB 2
#define TT 512
#define UU 48
#define DD 512
#define HH 1024
#define KK 128
#define SEG_ELEMS (BB*KK*TT)   // 131072 floats, first part of d_out

// Scratch (allocation-free rule: __device__ globals)
__device__ float g_img_pre[BB*TT*HH];           // [(b*T+t)][h] : img @ Wi^T (fp32)
__device__ float g_lab_pre[BB*UU*HH];           // [(b*U+u)][h] : lab @ Wl^T + b1 (fp32)
__device__ __nv_bfloat16 g_w2bf[KK*HH];         // W2 bf16, native (k,h) layout = B^T row-major

__device__ __forceinline__ float tanh_hw(float x){
    asm("tanh.approx.f32 %0, %0;" : "+f"(x)); return x;
}
__device__ __forceinline__ uint32_t smem_u32(const void* p){
    uint32_t a;
    asm("{ .reg .u64 t; cvta.to.shared.u64 t, %1; cvt.u32.u64 %0, t; }" : "=r"(a) : "l"(p));
    return a;
}
__device__ __forceinline__ void ldsm_x4(uint32_t* r, uint32_t addr){
    asm volatile("ldmatrix.sync.aligned.m8n8.x4.shared.b16 {%0,%1,%2,%3}, [%4];"
        : "=r"(r[0]), "=r"(r[1]), "=r"(r[2]), "=r"(r[3]) : "r"(addr));
}
__device__ __forceinline__ void mma16816(float* c, const uint32_t* a, uint32_t b0, uint32_t b1){
    asm volatile("mma.sync.aligned.m16n8k16.row.col.f32.bf16.bf16.f32 "
        "{%0,%1,%2,%3}, {%4,%5,%6,%7}, {%8,%9}, {%0,%1,%2,%3};"
        : "+f"(c[0]), "+f"(c[1]), "+f"(c[2]), "+f"(c[3])
        : "r"(a[0]), "r"(a[1]), "r"(a[2]), "r"(a[3]), "r"(b0), "r"(b1));
}
__device__ __forceinline__ void mma1688_tf32(float* c, const uint32_t* a, uint32_t b0, uint32_t b1){
    asm volatile("mma.sync.aligned.m16n8k8.row.col.f32.tf32.tf32.f32 "
        "{%0,%1,%2,%3}, {%4,%5,%6,%7}, {%8,%9}, {%0,%1,%2,%3};"
        : "+f"(c[0]), "+f"(c[1]), "+f"(c[2]), "+f"(c[3])
        : "r"(a[0]), "r"(a[1]), "r"(a[2]), "r"(a[3]), "r"(b0), "r"(b1));
}
__device__ __forceinline__ uint32_t sw_addr(uint32_t base, int row, int colb){
    uint32_t rel = (uint32_t)(row*128 + colb);
    return base + (rel ^ ((rel >> 3) & 0x70));
}
__device__ __forceinline__ void cp_async16(uint32_t dst, const void* src){
    asm volatile("cp.async.cg.shared.global [%0], [%1], 16;" :: "r"(dst), "l"(src));
}
__device__ __forceinline__ void cp_commit(){ asm volatile("cp.async.commit_group;" ::: "memory"); }
__device__ __forceinline__ void cp_wait0(){ asm volatile("cp.async.wait_group 0;" ::: "memory"); }
__device__ __forceinline__ uint32_t f2tf32(float x){
    uint32_t r; asm("cvt.rna.tf32.f32 %0, %1;" : "=r"(r) : "f"(x)); return r;
}
__device__ __forceinline__ float lds32(uint32_t addr){
    float v; asm volatile("ld.shared.f32 %0, [%1];" : "=f"(v) : "r"(addr)); return v;
}

// ---------------------------------------------------------------------------
// Prep kernel, tf32 tensor-core: 3 NT-GEMMs + W2 bf16 convert. 88 CTAs.
// (unchanged from R12 — measured good)
// ---------------------------------------------------------------------------
#define PSM_A0 0u
#define PSM_A1 16384u
#define PSM_B0 32768u
#define PSM_B1 49152u
#define PSM_TOTAL 65536

__global__ __launch_bounds__(256, 2) void prep_tc_kernel(
    const float* __restrict__ img, const float* __restrict__ lab,
    const float* __restrict__ W1, const float* __restrict__ b1,
    const float* __restrict__ convw, const float* __restrict__ convb,
    const float* __restrict__ masks, const float* __restrict__ W2,
    float* __restrict__ out)
{
    extern __shared__ char dsm[];
    const int bx  = blockIdx.x;
    const int tid = threadIdx.x;

    if (bx >= 80){
        int base = (bx - 80)*16384 + tid*4;
        #pragma unroll
        for (int q = 0; q < 16; q++){
            int i = base + q*1024;
            float4 wv = *(const float4*)&W2[i];
            __nv_bfloat162 p0 = __floats2bfloat162_rn(wv.x, wv.y);
            __nv_bfloat162 p1 = __floats2bfloat162_rn(wv.z, wv.w);
            uint2 u; u.x = *(uint32_t*)&p0; u.y = *(uint32_t*)&p1;
            *(uint2*)&g_w2bf[i] = u;
        }
        return;
    }

    const uint32_t sb = smem_u32(dsm);
    const float* A; const float* Bp;
    int ldb, M, m0, n0, job;
    if (bx < 64)      { job=0; A=img; Bp=W1+DD; ldb=2*DD; M=BB*TT; m0=(bx&7)*128;  n0=(bx>>3)*128; }
    else if (bx < 72) { job=1; A=lab; Bp=W1;    ldb=2*DD; M=BB*UU; m0=0;           n0=(bx-64)*128; }
    else              { job=2; A=img; Bp=convw; ldb=DD;   M=BB*TT; m0=(bx-72)*128; n0=0; }

    const int wid  = tid >> 5;
    const int lane = tid & 31;
    const int warp_m = wid & 3;
    const int warp_n = wid >> 2;
    const int lane4 = lane & 3;
    const int grp   = lane >> 2;

    const int r    = tid >> 1;
    const int cb0  = (tid & 1) * 16;
    const bool avalid = (m0 + r) < M;
    const float* arow = A  + (size_t)(m0 + r)*DD;
    const float* brow = Bp + (size_t)(n0 + r)*ldb;

    float acc[2][8][4];
    #pragma unroll
    for (int mi = 0; mi < 2; mi++)
        #pragma unroll
        for (int ni = 0; ni < 8; ni++)
            #pragma unroll
            for (int j = 0; j < 4; j++) acc[mi][ni][j] = 0.f;

    #pragma unroll
    for (int kk = 0; kk < 4; kk++){
        int col = cb0 + kk*4;
        float4 av = avalid ? *(const float4*)&arow[col] : make_float4(0,0,0,0);
        float4 bv = *(const float4*)&brow[col];
        uint4 at, bt;
        at.x = f2tf32(av.x); at.y = f2tf32(av.y); at.z = f2tf32(av.z); at.w = f2tf32(av.w);
        bt.x = f2tf32(bv.x); bt.y = f2tf32(bv.y); bt.z = f2tf32(bv.z); bt.w = f2tf32(bv.w);
        uint32_t aa = sw_addr(sb + PSM_A0, r, col*4);
        uint32_t ba = sw_addr(sb + PSM_B0, r, col*4);
        asm volatile("st.shared.v4.b32 [%0], {%1,%2,%3,%4};"
            :: "r"(aa), "r"(at.x), "r"(at.y), "r"(at.z), "r"(at.w));
        asm volatile("st.shared.v4.b32 [%0], {%1,%2,%3,%4};"
            :: "r"(ba), "r"(bt.x), "r"(bt.y), "r"(bt.z), "r"(bt.w));
    }
    __syncthreads();

    for (int c = 0; c < 16; c++){
        const int s  = c & 1;
        const int dn = c*32 + 32;
        const uint32_t Ab = sb + (s ? PSM_A1 : PSM_A0);
        const uint32_t Bb = sb + (s ? PSM_B1 : PSM_B0);
        const uint32_t An = sb + (s ? PSM_A0 : PSM_A1);
        const uint32_t Bn = sb + (s ? PSM_B0 : PSM_B1);

        #pragma unroll
        for (int kk = 0; kk < 4; kk++){
            float4 av, bv;
            if (c < 15){
                int col = dn + cb0 + kk*4;
                av = avalid ? *(const float4*)&arow[col] : make_float4(0,0,0,0);
                bv = *(const float4*)&brow[col];
            }
            const int ca = (kk*8 + lane4)*4;
            const int cc = (kk*8 + lane4 + 4)*4;
            uint32_t af[2][4];
            #pragma unroll
            for (int mi = 0; mi < 2; mi++){
                int rb = warp_m*32 + mi*16;
                af[mi][0] = __float_as_uint(lds32(sw_addr(Ab, rb + grp,     ca)));
                af[mi][1] = __float_as_uint(lds32(sw_addr(Ab, rb + grp + 8, ca)));
                af[mi][2] = __float_as_uint(lds32(sw_addr(Ab, rb + grp,     cc)));
                af[mi][3] = __float_as_uint(lds32(sw_addr(Ab, rb + grp + 8, cc)));
            }
            #pragma unroll
            for (int ni = 0; ni < 8; ni++){
                int rn = warp_n*64 + ni*8 + grp;
                uint32_t b0 = __float_as_uint(lds32(sw_addr(Bb, rn, ca)));
                uint32_t b1 = __float_as_uint(lds32(sw_addr(Bb, rn, cc)));
                mma1688_tf32(acc[0][ni], af[0], b0, b1);
                mma1688_tf32(acc[1][ni], af[1], b0, b1);
            }
            if (c < 15){
                int col = cb0 + kk*4;
                uint4 at, bt;
                at.x = f2tf32(av.x); at.y = f2tf32(av.y); at.z = f2tf32(av.z); at.w = f2tf32(av.w);
                bt.x = f2tf32(bv.x); bt.y = f2tf32(bv.y); bt.z = f2tf32(bv.z); bt.w = f2tf32(bv.w);
                asm volatile("st.shared.v4.b32 [%0], {%1,%2,%3,%4};"
                    :: "r"(sw_addr(An, r, col*4)), "r"(at.x), "r"(at.y), "r"(at.z), "r"(at.w));
                asm volatile("st.shared.v4.b32 [%0], {%1,%2,%3,%4};"
                    :: "r"(sw_addr(Bn, r, col*4)), "r"(bt.x), "r"(bt.y), "r"(bt.z), "r"(bt.w));
            }
        }
        __syncthreads();
    }

    if (job == 0){
        #pragma unroll
        for (int mi = 0; mi < 2; mi++)
            #pragma unroll
            for (int h = 0; h < 2; h++){
                int m = m0 + warp_m*32 + mi*16 + grp + 8*h;
                float* orow = g_img_pre + (size_t)m*HH + n0 + warp_n*64;
                #pragma unroll
                for (int ni = 0; ni < 8; ni++)
                    *(float2*)&orow[ni*8 + 2*lane4] =
                        make_float2(acc[mi][ni][2*h], acc[mi][ni][2*h+1]);
            }
    } else if (job == 1){
        #pragma unroll
        for (int mi = 0; mi < 2; mi++)
            #pragma unroll
            for (int h = 0; h < 2; h++){
                int m = warp_m*32 + mi*16 + grp + 8*h;
                if (m < BB*UU){
                    float* orow = g_lab_pre + (size_t)m*HH + n0 + warp_n*64;
                    #pragma unroll
                    for (int ni = 0; ni < 8; ni++){
                        int n = ni*8 + 2*lane4;
                        float2 bb = *(const float2*)&b1[n0 + warp_n*64 + n];
                        *(float2*)&orow[n] =
                            make_float2(acc[mi][ni][2*h] + bb.x, acc[mi][ni][2*h+1] + bb.y);
                    }
                }
            }
    } else {
        #pragma unroll
        for (int mi = 0; mi < 2; mi++)
            #pragma unroll
            for (int h = 0; h < 2; h++){
                int m = m0 + warp_m*32 + mi*16 + grp + 8*h;
                float mk = masks[m];
                int b = m >> 9, t = m & 511;
                #pragma unroll
                for (int ni = 0; ni < 8; ni++){
                    int n = warp_n*64 + ni*8 + 2*lane4;
                    float2 cbv = *(const float2*)&convb[n];
                    out[(b*KK + n  )*TT + t] = (acc[mi][ni][2*h  ] + cbv.x)*mk;
                    out[(b*KK + n+1)*TT + t] = (acc[mi][ni][2*h+1] + cbv.y)*mk;
                }
            }
    }
}

// ---------------------------------------------------------------------------
// Joint kernel: 64(t) x 128(k) tile, occ 3 (85-reg cap), bf16 HMMA.
// 768 CTAs (96 pairs x 8 t-tiles); 8 warps = 4(m:16 rows) x 2(n:64 cols),
// 32 accs/thread. Double-buffered; A prefetch split in two 8-float halves
// interleaved between kstep pairs (<=8 extra live regs).
// ---------------------------------------------------------------------------
#define JSM_A0   0u
#define JSM_A1   8192u
#define JSM_B0   16384u
#define JSM_B1   32768u
#define JSM_B2S  49152u
#define JSM_RM   49664u   // 2*64 floats
#define JSM_RS   50176u
#define JSM_TOTAL 50688

__global__ __launch_bounds__(256, 3)
void joint_mma_kernel(const float* __restrict__ b2, float* __restrict__ out)
{
    extern __shared__ char dsm[];
    const uint32_t sb = smem_u32(dsm);
    float* b2s  = (float*)(dsm + JSM_B2S);
    float* redm = (float*)(dsm + JSM_RM);
    float* reds = (float*)(dsm + JSM_RS);

    const int tid  = threadIdx.x;
    const int wid  = tid >> 5;
    const int lane = tid & 31;
    const int warp_m = wid & 3;     // 16 t-rows each
    const int warp_n = wid >> 2;    // 64 k-cols each
    const int lane4 = lane & 3;
    const int grp   = lane >> 2;

    const int pair = blockIdx.x >> 3;        // b*U+u
    const int t0   = (blockIdx.x & 7) * 64;
    const int b    = pair / UU;

    if (tid < KK) b2s[tid] = b2[tid];

    const float* imgp = g_img_pre + (size_t)(b*TT + t0)*HH;
    const float* labp = g_lab_pre + (size_t)pair*HH;

    // A staging role: row ra (0..63), 16 h-values at qa
    const int ra = tid >> 2;
    const int qa = (tid & 3) * 16;
    const uint32_t arel = (uint32_t)(ra*128 + qa*2);
    // B staging role: row rb (0..127), 32 h-values at hbB
    const int rb = tid >> 1;
    const int hbB = (tid & 1) * 32;
    const uint32_t brel = (uint32_t)(rb*128 + hbB*2);

    float acc[8][4];
    #pragma unroll
    for (int ni = 0; ni < 8; ni++)
        #pragma unroll
        for (int j = 0; j < 4; j++) acc[ni][j] = 0.f;

    // -------- prologue: stage chunk 0 into buffer 0 --------
    {
        const char* wsrc = (const char*)(g_w2bf + (size_t)rb*HH + hbB);
        #pragma unroll
        for (int j = 0; j < 4; j++){
            uint32_t rel = brel + j*16;
            cp_async16(sb + JSM_B0 + (rel ^ ((rel >> 3) & 0x70)), wsrc + j*16);
        }
        cp_commit();
        const float* ia = imgp + (size_t)ra*HH + qa;
        const float* la = labp + qa;
        #pragma unroll
        for (int j = 0; j < 2; j++){
            float4 i0 = *(const float4*)&ia[j*8];
            float4 i1 = *(const float4*)&ia[j*8+4];
            float4 l0 = *(const float4*)&la[j*8];
            float4 l1 = *(const float4*)&la[j*8+4];
            __nv_bfloat162 p0 = __floats2bfloat162_rn(tanh_hw(i0.x+l0.x), tanh_hw(i0.y+l0.y));
            __nv_bfloat162 p1 = __floats2bfloat162_rn(tanh_hw(i0.z+l0.z), tanh_hw(i0.w+l0.w));
            __nv_bfloat162 p2 = __floats2bfloat162_rn(tanh_hw(i1.x+l1.x), tanh_hw(i1.y+l1.y));
            __nv_bfloat162 p3 = __floats2bfloat162_rn(tanh_hw(i1.z+l1.z), tanh_hw(i1.w+l1.w));
            uint32_t rel = arel + j*16;
            uint32_t addr = sb + JSM_A0 + (rel ^ ((rel >> 3) & 0x70));
            asm volatile("st.shared.v4.b32 [%0], {%1,%2,%3,%4};"
                :: "r"(addr), "r"(*(uint32_t*)&p0), "r"(*(uint32_t*)&p1),
                   "r"(*(uint32_t*)&p2), "r"(*(uint32_t*)&p3));
        }
        cp_wait0();
    }
    __syncthreads();

    // -------- main loop --------
    for (int c = 0; c < 16; c++){
        const int s  = c & 1;
        const int hn = c*64 + 64;
        const uint32_t Ab = sb + (s ? JSM_A1 : JSM_A0);
        const uint32_t Bb = sb + (s ? JSM_B1 : JSM_B0);
        const uint32_t An = sb + (s ? JSM_A0 : JSM_A1);
        const uint32_t Bn = sb + (s ? JSM_B0 : JSM_B1);

        if (c < 15){
            const char* wsrc = (const char*)(g_w2bf + (size_t)rb*HH + hn + hbB);
            #pragma unroll
            for (int j = 0; j < 4; j++){
                uint32_t rel = brel + j*16;
                cp_async16(Bn + (rel ^ ((rel >> 3) & 0x70)), wsrc + j*16);
            }
            cp_commit();
        }

        // first half of A(c+1) prefetch
        float4 p0, p1;
        if (c < 15){
            const float* ia = imgp + (size_t)ra*HH + hn + qa;
            p0 = *(const float4*)&ia[0];
            p1 = *(const float4*)&ia[4];
        }

        #pragma unroll
        for (int half = 0; half < 2; half++){
            #pragma unroll
            for (int k2 = 0; k2 < 2; k2++){
                const int kk = half*2 + k2;
                const int colb = kk*32 + (lane >> 4)*16;
                uint32_t af[4];
                ldsm_x4(af, sw_addr(Ab, warp_m*16 + (lane & 15), colb));
                uint32_t bf[4][4];
                #pragma unroll
                for (int p = 0; p < 4; p++)
                    ldsm_x4(bf[p], sw_addr(Bb, warp_n*64 + p*16 + (lane & 15), colb));
                #pragma unroll
                for (int p = 0; p < 4; p++){
                    mma16816(acc[2*p  ], af, bf[p][0], bf[p][2]);
                    mma16816(acc[2*p+1], af, bf[p][1], bf[p][3]);
                }
            }
            // after each kstep pair: finish this half of A(c+1), start next half
            if (c < 15){
                const float* la = labp + hn + qa + half*8;
                float4 l0 = *(const float4*)&la[0];
                float4 l1 = *(const float4*)&la[4];
                __nv_bfloat162 q0 = __floats2bfloat162_rn(tanh_hw(p0.x+l0.x), tanh_hw(p0.y+l0.y));
                __nv_bfloat162 q1 = __floats2bfloat162_rn(tanh_hw(p0.z+l0.z), tanh_hw(p0.w+l0.w));
                __nv_bfloat162 q2 = __floats2bfloat162_rn(tanh_hw(p1.x+l1.x), tanh_hw(p1.y+l1.y));
                __nv_bfloat162 q3 = __floats2bfloat162_rn(tanh_hw(p1.z+l1.z), tanh_hw(p1.w+l1.w));
                uint32_t rel = arel + half*16;
                uint32_t addr = An + (rel ^ ((rel >> 3) & 0x70));
                asm volatile("st.shared.v4.b32 [%0], {%1,%2,%3,%4};"
                    :: "r"(addr), "r"(*(uint32_t*)&q0), "r"(*(uint32_t*)&q1),
                       "r"(*(uint32_t*)&q2), "r"(*(uint32_t*)&q3));
                if (half == 0){
                    const float* ia = imgp + (size_t)ra*HH + hn + qa + 8;
                    p0 = *(const float4*)&ia[0];
                    p1 = *(const float4*)&ia[4];
                }
            }
        }
        if (c < 15) cp_wait0();
        __syncthreads();
    }

    // ---- epilogue: +b2, log_softmax over k (row split across 2 n-warps) ----
    #pragma unroll
    for (int ni = 0; ni < 8; ni++){
        float2 bv = *(const float2*)&b2s[warp_n*64 + ni*8 + 2*lane4];
        acc[ni][0] += bv.x; acc[ni][1] += bv.y;
        acc[ni][2] += bv.x; acc[ni][3] += bv.y;
    }
    float rm[2];
    #pragma unroll
    for (int h = 0; h < 2; h++){
        float m = -1e30f;
        #pragma unroll
        for (int ni = 0; ni < 8; ni++)
            m = fmaxf(m, fmaxf(acc[ni][2*h], acc[ni][2*h+1]));
        #pragma unroll
        for (int d = 1; d < 4; d <<= 1)
            m = fmaxf(m, __shfl_xor_sync(0xffffffffu, m, d));
        rm[h] = m;
    }
    if (lane4 == 0){
        #pragma unroll
        for (int h = 0; h < 2; h++)
            redm[warp_n*64 + warp_m*16 + grp + 8*h] = rm[h];
    }
    __syncthreads();
    float mx[2], sm[2];
    #pragma unroll
    for (int h = 0; h < 2; h++){
        int row = warp_m*16 + grp + 8*h;
        mx[h] = fmaxf(redm[row], redm[64 + row]);
        float s = 0.f;
        #pragma unroll
        for (int ni = 0; ni < 8; ni++)
            s += __expf(acc[ni][2*h] - mx[h]) + __expf(acc[ni][2*h+1] - mx[h]);
        #pragma unroll
        for (int d = 1; d < 4; d <<= 1)
            s += __shfl_xor_sync(0xffffffffu, s, d);
        sm[h] = s;
    }
    if (lane4 == 0){
        #pragma unroll
        for (int h = 0; h < 2; h++)
            reds[warp_n*64 + warp_m*16 + grp + 8*h] = sm[h];
    }
    __syncthreads();
    float* outj = out + SEG_ELEMS + (size_t)(pair*TT + t0)*KK;
    #pragma unroll
    for (int h = 0; h < 2; h++){
        int row = warp_m*16 + grp + 8*h;
        float L = mx[h] + __logf(reds[row] + reds[64 + row]);
        float* orow = outj + row*KK + warp_n*64;
        #pragma unroll
        for (int ni = 0; ni < 8; ni++)
            *(float2*)&orow[ni*8 + 2*lane4] =
                make_float2(acc[ni][2*h] - L, acc[ni][2*h+1] - L);
    }
}

// ---------------------------------------------------------------------------
extern "C" void kernel_launch(void* const* d_in, const int* in_sizes, int n_in,
                              void* d_out, int out_size)
{
    (void)in_sizes; (void)n_in; (void)out_size;
    const float* img   = (const float*)d_in[0];  // (B,T,D)
    const float* lab   = (const float*)d_in[1];  // (B,U,D)
    const float* masks = (const float*)d_in[2];  // (B,1,T)
    const float* W1    = (const float*)d_in[3];  // (H,2D)
    const float* b1    = (const float*)d_in[4];  // (H)
    const float* W2    = (const float*)d_in[5];  // (K,H)
    const float* b2    = (const float*)d_in[6];  // (K)
    const float* convw = (const float*)d_in[7];  // (K,D)
    const float* convb = (const float*)d_in[8];  // (K)
    float* out = (float*)d_out;

    cudaFuncSetAttribute(prep_tc_kernel,
                         cudaFuncAttributeMaxDynamicSharedMemorySize, PSM_TOTAL);
    cudaFuncSetAttribute(joint_mma_kernel,
                         cudaFuncAttributeMaxDynamicSharedMemorySize, JSM_TOTAL);

    prep_tc_kernel<<<88, 256, PSM_TOTAL>>>(img, lab, W1, b1, convw, convb, masks, W2, out);
    joint_mma_kernel<<<768, 256, JSM_TOTAL>>>(b2, out);
}